// round 4
// baseline (speedup 1.0000x reference)
#include <cuda_runtime.h>

// ---------------------------------------------------------------------------
// VAE_CDDD_decoder round 4:
//   Round-3 structure (float4-packed weights, G+proj in SMEM, double-buffered
//   hidden state, 128 blocks x 256 thr x 8 rows) with ONE change:
//   depth-4 register prefetch on every weight stream, and the second stream
//   of each layer preloaded before the first loop (no cold-start bubble).
//   Math order is bit-identical to round 3.
// ---------------------------------------------------------------------------

#define BB   1024
#define SS   350
#define VV   41
#define ROWS 8
#define NBLK 128

typedef unsigned long long ull;

// ------------------------- device scratch ----------------------------------
__device__ __align__(16) float4 g_P0 [3 * 64 * 256];  // Whh0 packed [g][k4][t]
__device__ __align__(16) float4 g_P1i[3 * 64 * 128];  // Wih1 packed [g][k4][u]
__device__ __align__(16) float4 g_P1h[3 * 32 * 128];  // Whh1 packed
__device__ __align__(16) float4 g_P2i[3 * 32 * 32];   // Wih2 packed
__device__ __align__(16) float4 g_P2h[3 * 8 * 32];    // Whh2 packed
__device__ __align__(16) float  g_G  [VV * 768];      // fused emb->gi table
__device__ float g_WprojT[32 * VV];
__device__ float g_hinit [BB * 416];

// ------------------------- helpers -----------------------------------------
__device__ __forceinline__ ull splat2(float w) {
    ull r; asm("mov.b64 %0, {%1, %1};" : "=l"(r) : "f"(w)); return r;
}
__device__ __forceinline__ void fma2(ull& acc, ull a, ull b) {
    asm("fma.rn.f32x2 %0, %1, %2, %0;" : "+l"(acc) : "l"(a), "l"(b));
}
__device__ __forceinline__ float2 unpack2(ull v) {
    float2 f; asm("mov.b64 {%0, %1}, %2;" : "=f"(f.x), "=f"(f.y) : "l"(v)); return f;
}
__device__ __forceinline__ float sigm(float x) { return 1.0f / (1.0f + expf(-x)); }

// accumulate 3 gates x 4 row-pair accumulators for one k
#define GRU3(aX, aY, aZ, wx, wy, wzc, hA, hB) do { \
    ull w2x = splat2(wx), w2y = splat2(wy), w2z = splat2(wzc); \
    fma2(aX[0], w2x, hA.x); fma2(aX[1], w2x, hA.y); fma2(aX[2], w2x, hB.x); fma2(aX[3], w2x, hB.y); \
    fma2(aY[0], w2y, hA.x); fma2(aY[1], w2y, hA.y); fma2(aY[2], w2y, hB.x); fma2(aY[3], w2y, hB.y); \
    fma2(aZ[0], w2z, hA.x); fma2(aZ[1], w2z, hA.y); fma2(aZ[2], w2z, hB.x); fma2(aZ[3], w2z, hB.y); \
} while (0)

// 3 gates x 2 row-pair accumulators (4 rows) for one k
#define GRU3H(aX, aY, aZ, wx, wy, wzc, hA) do { \
    ull w2x = splat2(wx), w2y = splat2(wy), w2z = splat2(wzc); \
    fma2(aX[0], w2x, hA.x); fma2(aX[1], w2x, hA.y); \
    fma2(aY[0], w2y, hA.x); fma2(aY[1], w2y, hA.y); \
    fma2(aZ[0], w2z, hA.x); fma2(aZ[1], w2z, hA.y); \
} while (0)

// ------------------------- single precompute kernel -------------------------
__global__ void k_pre(
    const float* __restrict__ latent, const float* __restrict__ b_init,
    const float* __restrict__ W_init,
    const float* __restrict__ W_emb,  const float* __restrict__ b_emb,
    const float* __restrict__ bih0,
    const float* __restrict__ Wih0,   const float* __restrict__ Whh0,
    const float* __restrict__ Wih1,   const float* __restrict__ Whh1,
    const float* __restrict__ Wih2,   const float* __restrict__ Whh2,
    const float* __restrict__ W_proj)
{
    __shared__ float sh[4 * 512];
    const int b = blockIdx.x, tid = threadIdx.x;

    if (b < 256) {                       // hinit: 4 batch rows per block
        const int b0 = b * 4;
        for (int i = tid; i < 4 * 512; i += 256)
            sh[i] = latent[b0 * 512 + i];
        __syncthreads();
        for (int j = tid; j < 416; j += 256) {
            const float bi = b_init[j];
            float a0 = bi, a1 = bi, a2 = bi, a3 = bi;
            const float* w = W_init + j * 512;
            for (int k = 0; k < 512; k++) {
                float wv = w[k];
                a0 += wv * sh[k];
                a1 += wv * sh[512 + k];
                a2 += wv * sh[1024 + k];
                a3 += wv * sh[1536 + k];
            }
            g_hinit[(b0 + 0) * 416 + j] = a0;
            g_hinit[(b0 + 1) * 416 + j] = a1;
            g_hinit[(b0 + 2) * 416 + j] = a2;
            g_hinit[(b0 + 3) * 416 + j] = a3;
        }
    } else if (b < 297) {                // G table: one vocab row per block
        const int v = b - 256;
        for (int e = tid; e < 512; e += 256)
            sh[e] = W_emb[e * VV + v] + b_emb[e];
        __syncthreads();
        for (int f = tid; f < 768; f += 256) {
            float acc = bih0[f];
            const float* w = Wih0 + f * 512;
            for (int e = 0; e < 512; e++) acc += sh[e] * w[e];
            g_G[v * 768 + f] = acc;
        }
    } else if (b < 489) {                // pack Whh0 -> P0
        int idx = (b - 297) * 256 + tid;              // < 49152
        int t = idx & 255, k4 = (idx >> 8) & 63, g = idx >> 14;
        g_P0[idx] = *(const float4*)(Whh0 + (g * 256 + t) * 256 + k4 * 4);
    } else if (b < 585) {                // pack Wih1 -> P1i
        int idx = (b - 489) * 256 + tid;              // < 24576
        int u = idx & 127, k4 = (idx >> 7) & 63, g = idx >> 13;
        g_P1i[idx] = *(const float4*)(Wih1 + (g * 128 + u) * 256 + k4 * 4);
    } else if (b < 633) {                // pack Whh1 -> P1h
        int idx = (b - 585) * 256 + tid;              // < 12288
        int u = idx & 127, k4 = (idx >> 7) & 31, g = idx >> 12;
        g_P1h[idx] = *(const float4*)(Whh1 + (g * 128 + u) * 128 + k4 * 4);
    } else if (b < 645) {                // pack Wih2 -> P2i
        int idx = (b - 633) * 256 + tid;              // < 3072
        int u = idx & 31, k4 = (idx >> 5) & 31, g = idx >> 10;
        g_P2i[idx] = *(const float4*)(Wih2 + (g * 32 + u) * 128 + k4 * 4);
    } else if (b < 648) {                // pack Whh2 -> P2h
        int idx = (b - 645) * 256 + tid;              // < 768
        int u = idx & 31, k4 = (idx >> 5) & 7, g = idx >> 8;
        g_P2h[idx] = *(const float4*)(Whh2 + (g * 32 + u) * 32 + k4 * 4);
    } else {                             // proj transpose
        for (int idx = tid; idx < 32 * VV; idx += 256) {
            int k = idx / VV, v = idx - k * VV;
            g_WprojT[idx] = W_proj[v * 32 + k];
        }
    }
}

// ------------------------- main persistent kernel ---------------------------
#define SM_FLOATS (31488 + 4096 + 2048 + 512 + 1312 + 328 + 41)
#define SMEM_BYTES (SM_FLOATS * 4 + 2800)

__global__ __launch_bounds__(256, 1) void k_main(
    const int*   __restrict__ target,
    const float* __restrict__ bhh0,
    const float* __restrict__ bih1, const float* __restrict__ bhh1,
    const float* __restrict__ bih2, const float* __restrict__ bhh2,
    const float* __restrict__ bproj,
    float* __restrict__ out, float* __restrict__ pred, int write_pred)
{
    extern __shared__ __align__(16) char smraw[];
    float* Gs    = (float*)smraw;        // 31488
    float* h0b   = Gs    + 31488;        // 2 * 2048
    float* h1b   = h0b   + 4096;         // 2 * 1024
    float* h2b   = h1b   + 2048;         // 2 * 256
    float* projS = h2b   + 512;          // 1312
    float* slog  = projS + 1312;         // 328
    float* bprjS = slog  + 328;          // 41
    unsigned char* stok = (unsigned char*)(bprjS + 41);   // 2800

    const int t    = threadIdx.x;
    const int row0 = blockIdx.x * ROWS;

    // ---- stage G + proj into SMEM ----
    {
        float4* Gd = (float4*)Gs;
        const float4* Gg = (const float4*)g_G;
        for (int i = t; i < 31488 / 4; i += 256) Gd[i] = Gg[i];
    }
    for (int i = t; i < 1312; i += 256) projS[i] = g_WprojT[i];
    if (t < VV) bprjS[t] = bproj[t];

    // ---- initial hidden state into buffer 0 ----
    #pragma unroll
    for (int r = 0; r < ROWS; r++)
        h0b[t * 8 + r] = g_hinit[(row0 + r) * 416 + t];
    if (t < 128) {
        #pragma unroll
        for (int r = 0; r < ROWS; r++)
            h1b[t * 8 + r] = g_hinit[(row0 + r) * 416 + 256 + t];
    }
    if (t < 32) {
        #pragma unroll
        for (int r = 0; r < ROWS; r++)
            h2b[t * 8 + r] = g_hinit[(row0 + r) * 416 + 384 + t];
    }
    // ---- tokens (teacher forcing: tok[0]=SOS, else target[:,s]) ----
    for (int i = t; i < SS * ROWS; i += 256) {
        int s = i >> 3, r = i & 7;
        int tk = (s == 0) ? 1 : target[(row0 + r) * SS + s];
        stok[i] = (unsigned char)tk;
    }

    // ---- biases in registers ----
    const float b0r = bhh0[t], b0z = bhh0[t + 256], b0n = bhh0[t + 512];
    float b1r = 0.f, b1z = 0.f, b1i = 0.f, b1h = 0.f;
    if (t < 128) {
        b1r = bih1[t] + bhh1[t];
        b1z = bih1[t + 128] + bhh1[t + 128];
        b1i = bih1[t + 256];
        b1h = bhh1[t + 256];
    }
    int u2 = t & 31, rb2 = (t >> 5) * 4;
    float b2r = 0.f, b2z = 0.f, b2i = 0.f, b2h = 0.f;
    if (t < 64) {
        b2r = bih2[u2] + bhh2[u2];
        b2z = bih2[u2 + 32] + bhh2[u2 + 32];
        b2i = bih2[u2 + 64];
        b2h = bhh2[u2 + 64];
    }
    __syncthreads();

    int cur = 0;
    for (int step = 0; step < SS; ++step) {
        const int nxt = cur ^ 1;
        const float* h0c = h0b + cur * 2048;
        float*       h0n = h0b + nxt * 2048;
        const float* h1c = h1b + cur * 1024;
        float*       h1n = h1b + nxt * 1024;
        const float* h2c = h2b + cur * 256;
        float*       h2n = h2b + nxt * 256;

        // ================= layer 0 =================
        float gir[8], giz[8], gin[8];
        #pragma unroll
        for (int r = 0; r < ROWS; r++) {
            int base = (int)stok[step * 8 + r] * 768 + t;
            gir[r] = Gs[base]; giz[r] = Gs[base + 256]; gin[r] = Gs[base + 512];
        }
        ull ar[4], az[4], an[4];
        #pragma unroll
        for (int p = 0; p < 4; p++) { ar[p] = splat2(b0r); az[p] = splat2(b0z); an[p] = splat2(b0n); }
        {
            const float4* Pr = g_P0;
            const float4* Pz = g_P0 + 16384;
            const float4* Pn = g_P0 + 32768;
            float4 wr[4], wz[4], wn[4];
            #pragma unroll
            for (int i = 0; i < 4; i++) {
                int o = i * 256 + t;
                wr[i] = __ldg(&Pr[o]); wz[i] = __ldg(&Pz[o]); wn[i] = __ldg(&Pn[o]);
            }
            #pragma unroll 4
            for (int k4 = 0; k4 < 64; ++k4) {
                const int s = k4 & 3;
                float4 cr = wr[s], cz = wz[s], cn = wn[s];
                if (k4 < 60) {
                    int o = (k4 + 4) * 256 + t;
                    wr[s] = __ldg(&Pr[o]); wz[s] = __ldg(&Pz[o]); wn[s] = __ldg(&Pn[o]);
                }
                const ulonglong2* hp = (const ulonglong2*)(h0c + k4 * 32);
                ulonglong2 hA0 = hp[0], hB0 = hp[1], hA1 = hp[2], hB1 = hp[3];
                ulonglong2 hA2 = hp[4], hB2 = hp[5], hA3 = hp[6], hB3 = hp[7];
                GRU3(ar, az, an, cr.x, cz.x, cn.x, hA0, hB0);
                GRU3(ar, az, an, cr.y, cz.y, cn.y, hA1, hB1);
                GRU3(ar, az, an, cr.z, cz.z, cn.z, hA2, hB2);
                GRU3(ar, az, an, cr.w, cz.w, cn.w, hA3, hB3);
            }
        }
        {
            float h0new[8];
            #pragma unroll
            for (int p = 0; p < 4; p++) {
                float2 fr = unpack2(ar[p]), fz = unpack2(az[p]), fn = unpack2(an[p]);
                int i0 = 2 * p, i1 = i0 + 1;
                float rg = sigm(gir[i0] + fr.x);
                float zg = sigm(giz[i0] + fz.x);
                float ng = tanhf(gin[i0] + rg * fn.x);
                h0new[i0] = (1.0f - zg) * ng + zg * h0c[t * 8 + i0];
                rg = sigm(gir[i1] + fr.y);
                zg = sigm(giz[i1] + fz.y);
                ng = tanhf(gin[i1] + rg * fn.y);
                h0new[i1] = (1.0f - zg) * ng + zg * h0c[t * 8 + i1];
            }
            *(float4*)(h0n + t * 8)     = make_float4(h0new[0], h0new[1], h0new[2], h0new[3]);
            *(float4*)(h0n + t * 8 + 4) = make_float4(h0new[4], h0new[5], h0new[6], h0new[7]);
        }
        __syncthreads();                                   // S1

        // ================= layer 1 (threads 0..127, unit=t, 8 rows) ========
        if (t < 128) {
            ull a1r[4], a1z[4], a1i[4], a1h[4];
            #pragma unroll
            for (int p = 0; p < 4; p++) {
                a1r[p] = splat2(b1r); a1z[p] = splat2(b1z);
                a1i[p] = splat2(b1i); a1h[p] = splat2(b1h);
            }
            const float4* Qr = g_P1i;
            const float4* Qz = g_P1i + 8192;
            const float4* Qn = g_P1i + 16384;
            const float4* Rr = g_P1h;
            const float4* Rz = g_P1h + 4096;
            const float4* Rn = g_P1h + 8192;
            // preload BOTH streams depth-4 so the gh loop starts warm
            float4 qr[4], qz[4], qn[4], rr[4], rz[4], rn[4];
            #pragma unroll
            for (int i = 0; i < 4; i++) {
                int o = i * 128 + t;
                qr[i] = __ldg(&Qr[o]); qz[i] = __ldg(&Qz[o]); qn[i] = __ldg(&Qn[o]);
                rr[i] = __ldg(&Rr[o]); rz[i] = __ldg(&Rz[o]); rn[i] = __ldg(&Rn[o]);
            }
            #pragma unroll 4
            for (int k4 = 0; k4 < 64; ++k4) {            // gi side: x = h0 new
                const int s = k4 & 3;
                float4 cr = qr[s], cz = qz[s], cn = qn[s];
                if (k4 < 60) {
                    int o = (k4 + 4) * 128 + t;
                    qr[s] = __ldg(&Qr[o]); qz[s] = __ldg(&Qz[o]); qn[s] = __ldg(&Qn[o]);
                }
                const ulonglong2* hp = (const ulonglong2*)(h0n + k4 * 32);
                ulonglong2 hA0 = hp[0], hB0 = hp[1], hA1 = hp[2], hB1 = hp[3];
                ulonglong2 hA2 = hp[4], hB2 = hp[5], hA3 = hp[6], hB3 = hp[7];
                GRU3(a1r, a1z, a1i, cr.x, cz.x, cn.x, hA0, hB0);
                GRU3(a1r, a1z, a1i, cr.y, cz.y, cn.y, hA1, hB1);
                GRU3(a1r, a1z, a1i, cr.z, cz.z, cn.z, hA2, hB2);
                GRU3(a1r, a1z, a1i, cr.w, cz.w, cn.w, hA3, hB3);
            }
            #pragma unroll 4
            for (int k4 = 0; k4 < 32; ++k4) {            // gh side: h1 old
                const int s = k4 & 3;
                float4 cr = rr[s], cz = rz[s], cn = rn[s];
                if (k4 < 28) {
                    int o = (k4 + 4) * 128 + t;
                    rr[s] = __ldg(&Rr[o]); rz[s] = __ldg(&Rz[o]); rn[s] = __ldg(&Rn[o]);
                }
                const ulonglong2* hp = (const ulonglong2*)(h1c + k4 * 32);
                ulonglong2 hA0 = hp[0], hB0 = hp[1], hA1 = hp[2], hB1 = hp[3];
                ulonglong2 hA2 = hp[4], hB2 = hp[5], hA3 = hp[6], hB3 = hp[7];
                GRU3(a1r, a1z, a1h, cr.x, cz.x, cn.x, hA0, hB0);
                GRU3(a1r, a1z, a1h, cr.y, cz.y, cn.y, hA1, hB1);
                GRU3(a1r, a1z, a1h, cr.z, cz.z, cn.z, hA2, hB2);
                GRU3(a1r, a1z, a1h, cr.w, cz.w, cn.w, hA3, hB3);
            }
            float h1new[8];
            #pragma unroll
            for (int p = 0; p < 4; p++) {
                float2 fr = unpack2(a1r[p]), fz = unpack2(a1z[p]);
                float2 fi = unpack2(a1i[p]), fh = unpack2(a1h[p]);
                int i0 = 2 * p, i1 = i0 + 1;
                float rg = sigm(fr.x), zg = sigm(fz.x);
                float ng = tanhf(fi.x + rg * fh.x);
                h1new[i0] = (1.0f - zg) * ng + zg * h1c[t * 8 + i0];
                rg = sigm(fr.y); zg = sigm(fz.y);
                ng = tanhf(fi.y + rg * fh.y);
                h1new[i1] = (1.0f - zg) * ng + zg * h1c[t * 8 + i1];
            }
            *(float4*)(h1n + t * 8)     = make_float4(h1new[0], h1new[1], h1new[2], h1new[3]);
            *(float4*)(h1n + t * 8 + 4) = make_float4(h1new[4], h1new[5], h1new[6], h1new[7]);
        }
        __syncthreads();                                   // S2

        // ================= layer 2 (threads 0..63, unit=t&31, 4 rows) ======
        if (t < 64) {
            ull a2r[2], a2z[2], a2i[2], a2h[2];
            a2r[0] = a2r[1] = splat2(b2r);
            a2z[0] = a2z[1] = splat2(b2z);
            a2i[0] = a2i[1] = splat2(b2i);
            a2h[0] = a2h[1] = splat2(b2h);
            const float4* Qr = g_P2i;
            const float4* Qz = g_P2i + 1024;
            const float4* Qn = g_P2i + 2048;
            const float4* Rr = g_P2h;
            const float4* Rz = g_P2h + 256;
            const float4* Rn = g_P2h + 512;
            float4 qr[4], qz[4], qn[4], rr[4], rz[4], rn[4];
            #pragma unroll
            for (int i = 0; i < 4; i++) {
                int o = i * 32 + u2;
                qr[i] = __ldg(&Qr[o]); qz[i] = __ldg(&Qz[o]); qn[i] = __ldg(&Qn[o]);
                rr[i] = __ldg(&Rr[o]); rz[i] = __ldg(&Rz[o]); rn[i] = __ldg(&Rn[o]);
            }
            #pragma unroll 4
            for (int k4 = 0; k4 < 32; ++k4) {            // gi side: h1 new
                const int s = k4 & 3;
                float4 cr = qr[s], cz = qz[s], cn = qn[s];
                if (k4 < 28) {
                    int o = (k4 + 4) * 32 + u2;
                    qr[s] = __ldg(&Qr[o]); qz[s] = __ldg(&Qz[o]); qn[s] = __ldg(&Qn[o]);
                }
                ulonglong2 hA0 = *(const ulonglong2*)(h1n + (k4 * 4 + 0) * 8 + rb2);
                ulonglong2 hA1 = *(const ulonglong2*)(h1n + (k4 * 4 + 1) * 8 + rb2);
                ulonglong2 hA2 = *(const ulonglong2*)(h1n + (k4 * 4 + 2) * 8 + rb2);
                ulonglong2 hA3 = *(const ulonglong2*)(h1n + (k4 * 4 + 3) * 8 + rb2);
                GRU3H(a2r, a2z, a2i, cr.x, cz.x, cn.x, hA0);
                GRU3H(a2r, a2z, a2i, cr.y, cz.y, cn.y, hA1);
                GRU3H(a2r, a2z, a2i, cr.z, cz.z, cn.z, hA2);
                GRU3H(a2r, a2z, a2i, cr.w, cz.w, cn.w, hA3);
            }
            #pragma unroll 4
            for (int k4 = 0; k4 < 8; ++k4) {             // gh side: h2 old
                const int s = k4 & 3;
                float4 cr = rr[s], cz = rz[s], cn = rn[s];
                if (k4 < 4) {
                    int o = (k4 + 4) * 32 + u2;
                    rr[s] = __ldg(&Rr[o]); rz[s] = __ldg(&Rz[o]); rn[s] = __ldg(&Rn[o]);
                }
                ulonglong2 hA0 = *(const ulonglong2*)(h2c + (k4 * 4 + 0) * 8 + rb2);
                ulonglong2 hA1 = *(const ulonglong2*)(h2c + (k4 * 4 + 1) * 8 + rb2);
                ulonglong2 hA2 = *(const ulonglong2*)(h2c + (k4 * 4 + 2) * 8 + rb2);
                ulonglong2 hA3 = *(const ulonglong2*)(h2c + (k4 * 4 + 3) * 8 + rb2);
                GRU3H(a2r, a2z, a2h, cr.x, cz.x, cn.x, hA0);
                GRU3H(a2r, a2z, a2h, cr.y, cz.y, cn.y, hA1);
                GRU3H(a2r, a2z, a2h, cr.z, cz.z, cn.z, hA2);
                GRU3H(a2r, a2z, a2h, cr.w, cz.w, cn.w, hA3);
            }
            float h2new[4];
            #pragma unroll
            for (int p = 0; p < 2; p++) {
                float2 fr = unpack2(a2r[p]), fz = unpack2(a2z[p]);
                float2 fi = unpack2(a2i[p]), fh = unpack2(a2h[p]);
                int j0 = 2 * p, j1 = j0 + 1;
                float rg = sigm(fr.x), zg = sigm(fz.x);
                float ng = tanhf(fi.x + rg * fh.x);
                h2new[j0] = (1.0f - zg) * ng + zg * h2c[u2 * 8 + rb2 + j0];
                rg = sigm(fr.y); zg = sigm(fz.y);
                ng = tanhf(fi.y + rg * fh.y);
                h2new[j1] = (1.0f - zg) * ng + zg * h2c[u2 * 8 + rb2 + j1];
            }
            *(float4*)(h2n + u2 * 8 + rb2) = make_float4(h2new[0], h2new[1], h2new[2], h2new[3]);
        }
        __syncthreads();                                   // S3

        // ================= projection + argmax =============================
        for (int idx = t; idx < VV * ROWS; idx += 256) {
            int r = idx / VV, v = idx - r * VV;
            float acc = bprjS[v];
            #pragma unroll
            for (int k = 0; k < 32; k++)
                acc += h2n[k * 8 + r] * projS[k * VV + v];
            out[((size_t)(row0 + r) * SS + step) * VV + v] = acc;
            slog[v * 8 + r] = acc;
        }
        __syncthreads();                                   // S4
        if (t < ROWS && write_pred) {
            float best = slog[t]; int bi = 0;
            #pragma unroll
            for (int v = 1; v < VV; v++) {
                float x = slog[v * 8 + t];
                if (x > best) { best = x; bi = v; }
            }
            pred[(size_t)(row0 + t) * SS + step] = (float)bi;
        }
        cur = nxt;
    }
}

// ------------------------- launch ------------------------------------------
extern "C" void kernel_launch(void* const* d_in, const int* in_sizes, int n_in,
                              void* d_out, int out_size) {
    const float* latent = (const float*)d_in[0];
    const int*   target = (const int*)  d_in[1];
    const float* W_emb  = (const float*)d_in[2];
    const float* b_emb  = (const float*)d_in[3];
    const float* W_init = (const float*)d_in[4];
    const float* b_init = (const float*)d_in[5];
    const float* Wih0   = (const float*)d_in[6];
    const float* Whh0   = (const float*)d_in[7];
    const float* bih0   = (const float*)d_in[8];
    const float* bhh0   = (const float*)d_in[9];
    const float* Wih1   = (const float*)d_in[10];
    const float* Whh1   = (const float*)d_in[11];
    const float* bih1   = (const float*)d_in[12];
    const float* bhh1   = (const float*)d_in[13];
    const float* Wih2   = (const float*)d_in[14];
    const float* Whh2   = (const float*)d_in[15];
    const float* bih2   = (const float*)d_in[16];
    const float* bhh2   = (const float*)d_in[17];
    const float* W_proj = (const float*)d_in[18];
    const float* b_proj = (const float*)d_in[19];
    (void)in_sizes; (void)n_in;

    k_pre<<<649, 256>>>(latent, b_init, W_init, W_emb, b_emb, bih0,
                        Wih0, Whh0, Wih1, Whh1, Wih2, Whh2, W_proj);

    cudaFuncSetAttribute(k_main, cudaFuncAttributeMaxDynamicSharedMemorySize,
                         SMEM_BYTES);

    float* out  = (float*)d_out;
    float* pred = out + (size_t)BB * SS * VV;
    int wp = (out_size >= (int)((size_t)BB * SS * VV + (size_t)BB * SS)) ? 1 : 0;

    k_main<<<NBLK, 256, SMEM_BYTES>>>(target, bhh0, bih1, bhh1, bih2, bhh2,
                                      b_proj, out, pred, wp);
}

// round 6
// speedup vs baseline: 1.6246x; 1.6246x over previous
#include <cuda_runtime.h>

// ---------------------------------------------------------------------------
// VAE_CDDD_decoder round 5:
//   Round-3 structure (float4-packed weights, depth-1 prefetch, G+proj in
//   SMEM, double-buffered hidden state, 128 blocks x 256 thr x 8 rows),
//   with layer 1 spread across ALL 256 threads (128 units x 2 row-halves)
//   and layer 2 across 128 threads (32 units x 4 row-pairs).
//   Accumulation order per output is bit-identical to round 3.
// ---------------------------------------------------------------------------

#define BB   1024
#define SS   350
#define VV   41
#define ROWS 8
#define NBLK 128

typedef unsigned long long ull;

// ------------------------- device scratch ----------------------------------
__device__ __align__(16) float4 g_P0 [3 * 64 * 256];  // Whh0 packed [g][k4][t]
__device__ __align__(16) float4 g_P1i[3 * 64 * 128];  // Wih1 packed [g][k4][u]
__device__ __align__(16) float4 g_P1h[3 * 32 * 128];  // Whh1 packed
__device__ __align__(16) float4 g_P2i[3 * 32 * 32];   // Wih2 packed
__device__ __align__(16) float4 g_P2h[3 * 8 * 32];    // Whh2 packed
__device__ __align__(16) float  g_G  [VV * 768];      // fused emb->gi table
__device__ float g_WprojT[32 * VV];
__device__ float g_hinit [BB * 416];

// ------------------------- helpers -----------------------------------------
__device__ __forceinline__ ull splat2(float w) {
    ull r; asm("mov.b64 %0, {%1, %1};" : "=l"(r) : "f"(w)); return r;
}
__device__ __forceinline__ void fma2(ull& acc, ull a, ull b) {
    asm("fma.rn.f32x2 %0, %1, %2, %0;" : "+l"(acc) : "l"(a), "l"(b));
}
__device__ __forceinline__ float2 unpack2(ull v) {
    float2 f; asm("mov.b64 {%0, %1}, %2;" : "=f"(f.x), "=f"(f.y) : "l"(v)); return f;
}
__device__ __forceinline__ float sigm(float x) { return 1.0f / (1.0f + expf(-x)); }

// accumulate 3 gates x 4 row-pair accumulators (8 rows) for one k
#define GRU3(aX, aY, aZ, wx, wy, wzc, hA, hB) do { \
    ull w2x = splat2(wx), w2y = splat2(wy), w2z = splat2(wzc); \
    fma2(aX[0], w2x, hA.x); fma2(aX[1], w2x, hA.y); fma2(aX[2], w2x, hB.x); fma2(aX[3], w2x, hB.y); \
    fma2(aY[0], w2y, hA.x); fma2(aY[1], w2y, hA.y); fma2(aY[2], w2y, hB.x); fma2(aY[3], w2y, hB.y); \
    fma2(aZ[0], w2z, hA.x); fma2(aZ[1], w2z, hA.y); fma2(aZ[2], w2z, hB.x); fma2(aZ[3], w2z, hB.y); \
} while (0)

// 3 gates x 2 accumulators (4 rows) for one k
#define GRU3H(aX, aY, aZ, wx, wy, wzc, hA) do { \
    ull w2x = splat2(wx), w2y = splat2(wy), w2z = splat2(wzc); \
    fma2(aX[0], w2x, hA.x); fma2(aX[1], w2x, hA.y); \
    fma2(aY[0], w2y, hA.x); fma2(aY[1], w2y, hA.y); \
    fma2(aZ[0], w2z, hA.x); fma2(aZ[1], w2z, hA.y); \
} while (0)

// 3 gates x 1 accumulator (2 rows) for one k
#define GRU3Q(aX, aY, aZ, wx, wy, wzc, hv) do { \
    ull w2x = splat2(wx), w2y = splat2(wy), w2z = splat2(wzc); \
    fma2(aX, w2x, hv); \
    fma2(aY, w2y, hv); \
    fma2(aZ, w2z, hv); \
} while (0)

// ------------------------- single precompute kernel -------------------------
__global__ void k_pre(
    const float* __restrict__ latent, const float* __restrict__ b_init,
    const float* __restrict__ W_init,
    const float* __restrict__ W_emb,  const float* __restrict__ b_emb,
    const float* __restrict__ bih0,
    const float* __restrict__ Wih0,   const float* __restrict__ Whh0,
    const float* __restrict__ Wih1,   const float* __restrict__ Whh1,
    const float* __restrict__ Wih2,   const float* __restrict__ Whh2,
    const float* __restrict__ W_proj)
{
    __shared__ float sh[4 * 512];
    const int b = blockIdx.x, tid = threadIdx.x;

    if (b < 256) {                       // hinit: 4 batch rows per block
        const int b0 = b * 4;
        for (int i = tid; i < 4 * 512; i += 256)
            sh[i] = latent[b0 * 512 + i];
        __syncthreads();
        for (int j = tid; j < 416; j += 256) {
            const float bi = b_init[j];
            float a0 = bi, a1 = bi, a2 = bi, a3 = bi;
            const float* w = W_init + j * 512;
            for (int k = 0; k < 512; k++) {
                float wv = w[k];
                a0 += wv * sh[k];
                a1 += wv * sh[512 + k];
                a2 += wv * sh[1024 + k];
                a3 += wv * sh[1536 + k];
            }
            g_hinit[(b0 + 0) * 416 + j] = a0;
            g_hinit[(b0 + 1) * 416 + j] = a1;
            g_hinit[(b0 + 2) * 416 + j] = a2;
            g_hinit[(b0 + 3) * 416 + j] = a3;
        }
    } else if (b < 297) {                // G table: one vocab row per block
        const int v = b - 256;
        for (int e = tid; e < 512; e += 256)
            sh[e] = W_emb[e * VV + v] + b_emb[e];
        __syncthreads();
        for (int f = tid; f < 768; f += 256) {
            float acc = bih0[f];
            const float* w = Wih0 + f * 512;
            for (int e = 0; e < 512; e++) acc += sh[e] * w[e];
            g_G[v * 768 + f] = acc;
        }
    } else if (b < 489) {                // pack Whh0 -> P0
        int idx = (b - 297) * 256 + tid;              // < 49152
        int t = idx & 255, k4 = (idx >> 8) & 63, g = idx >> 14;
        g_P0[idx] = *(const float4*)(Whh0 + (g * 256 + t) * 256 + k4 * 4);
    } else if (b < 585) {                // pack Wih1 -> P1i
        int idx = (b - 489) * 256 + tid;              // < 24576
        int u = idx & 127, k4 = (idx >> 7) & 63, g = idx >> 13;
        g_P1i[idx] = *(const float4*)(Wih1 + (g * 128 + u) * 256 + k4 * 4);
    } else if (b < 633) {                // pack Whh1 -> P1h
        int idx = (b - 585) * 256 + tid;              // < 12288
        int u = idx & 127, k4 = (idx >> 7) & 31, g = idx >> 12;
        g_P1h[idx] = *(const float4*)(Whh1 + (g * 128 + u) * 128 + k4 * 4);
    } else if (b < 645) {                // pack Wih2 -> P2i
        int idx = (b - 633) * 256 + tid;              // < 3072
        int u = idx & 31, k4 = (idx >> 5) & 31, g = idx >> 10;
        g_P2i[idx] = *(const float4*)(Wih2 + (g * 32 + u) * 128 + k4 * 4);
    } else if (b < 648) {                // pack Whh2 -> P2h
        int idx = (b - 645) * 256 + tid;              // < 768
        int u = idx & 31, k4 = (idx >> 5) & 7, g = idx >> 8;
        g_P2h[idx] = *(const float4*)(Whh2 + (g * 32 + u) * 32 + k4 * 4);
    } else {                             // proj transpose
        for (int idx = tid; idx < 32 * VV; idx += 256) {
            int k = idx / VV, v = idx - k * VV;
            g_WprojT[idx] = W_proj[v * 32 + k];
        }
    }
}

// ------------------------- main persistent kernel ---------------------------
#define SM_FLOATS (31488 + 4096 + 2048 + 512 + 1312 + 328 + 41)
#define SMEM_BYTES (SM_FLOATS * 4 + 2800)

__global__ __launch_bounds__(256, 1) void k_main(
    const int*   __restrict__ target,
    const float* __restrict__ bhh0,
    const float* __restrict__ bih1, const float* __restrict__ bhh1,
    const float* __restrict__ bih2, const float* __restrict__ bhh2,
    const float* __restrict__ bproj,
    float* __restrict__ out, float* __restrict__ pred, int write_pred)
{
    extern __shared__ __align__(16) char smraw[];
    float* Gs    = (float*)smraw;        // 31488
    float* h0b   = Gs    + 31488;        // 2 * 2048
    float* h1b   = h0b   + 4096;         // 2 * 1024
    float* h2b   = h1b   + 2048;         // 2 * 256
    float* projS = h2b   + 512;          // 1312
    float* slog  = projS + 1312;         // 328
    float* bprjS = slog  + 328;          // 41
    unsigned char* stok = (unsigned char*)(bprjS + 41);   // 2800

    const int t    = threadIdx.x;
    const int row0 = blockIdx.x * ROWS;

    // ---- stage G + proj into SMEM ----
    {
        float4* Gd = (float4*)Gs;
        const float4* Gg = (const float4*)g_G;
        for (int i = t; i < 31488 / 4; i += 256) Gd[i] = Gg[i];
    }
    for (int i = t; i < 1312; i += 256) projS[i] = g_WprojT[i];
    if (t < VV) bprjS[t] = bproj[t];

    // ---- initial hidden state into buffer 0 ----
    #pragma unroll
    for (int r = 0; r < ROWS; r++)
        h0b[t * 8 + r] = g_hinit[(row0 + r) * 416 + t];
    if (t < 128) {
        #pragma unroll
        for (int r = 0; r < ROWS; r++)
            h1b[t * 8 + r] = g_hinit[(row0 + r) * 416 + 256 + t];
    }
    if (t < 32) {
        #pragma unroll
        for (int r = 0; r < ROWS; r++)
            h2b[t * 8 + r] = g_hinit[(row0 + r) * 416 + 384 + t];
    }
    // ---- tokens (teacher forcing: tok[0]=SOS, else target[:,s]) ----
    for (int i = t; i < SS * ROWS; i += 256) {
        int s = i >> 3, r = i & 7;
        int tk = (s == 0) ? 1 : target[(row0 + r) * SS + s];
        stok[i] = (unsigned char)tk;
    }

    // ---- thread mappings + biases in registers ----
    const float b0r = bhh0[t], b0z = bhh0[t + 256], b0n = bhh0[t + 512];

    const int u1   = t & 127;            // layer-1 unit
    const int rb1  = (t >> 7) * 4;       // layer-1 row base (0 or 4)
    const float b1r = bih1[u1] + bhh1[u1];
    const float b1z = bih1[u1 + 128] + bhh1[u1 + 128];
    const float b1i = bih1[u1 + 256];
    const float b1h = bhh1[u1 + 256];

    const int u2  = t & 31;              // layer-2 unit (threads 0..127)
    const int rb2 = ((t >> 5) & 3) * 2;  // layer-2 row base (0,2,4,6)
    float b2r = 0.f, b2z = 0.f, b2i = 0.f, b2h = 0.f;
    if (t < 128) {
        b2r = bih2[u2] + bhh2[u2];
        b2z = bih2[u2 + 32] + bhh2[u2 + 32];
        b2i = bih2[u2 + 64];
        b2h = bhh2[u2 + 64];
    }
    __syncthreads();

    int cur = 0;
    for (int step = 0; step < SS; ++step) {
        const int nxt = cur ^ 1;
        const float* h0c = h0b + cur * 2048;
        float*       h0n = h0b + nxt * 2048;
        const float* h1c = h1b + cur * 1024;
        float*       h1n = h1b + nxt * 1024;
        const float* h2c = h2b + cur * 256;
        float*       h2n = h2b + nxt * 256;

        // ================= layer 0 (256 threads, unit=t, 8 rows) ==========
        float gir[8], giz[8], gin[8];
        #pragma unroll
        for (int r = 0; r < ROWS; r++) {
            int base = (int)stok[step * 8 + r] * 768 + t;
            gir[r] = Gs[base]; giz[r] = Gs[base + 256]; gin[r] = Gs[base + 512];
        }
        ull ar[4], az[4], an[4];
        #pragma unroll
        for (int p = 0; p < 4; p++) { ar[p] = splat2(b0r); az[p] = splat2(b0z); an[p] = splat2(b0n); }
        {
            const float4* Pr = g_P0;
            const float4* Pz = g_P0 + 16384;
            const float4* Pn = g_P0 + 32768;
            float4 fwr = __ldg(&Pr[t]), fwz = __ldg(&Pz[t]), fwn = __ldg(&Pn[t]);
            #pragma unroll 4
            for (int k4 = 0; k4 < 64; ++k4) {
                float4 wr = fwr, wz = fwz, wn = fwn;
                if (k4 < 63) {
                    int o = (k4 + 1) * 256 + t;
                    fwr = __ldg(&Pr[o]); fwz = __ldg(&Pz[o]); fwn = __ldg(&Pn[o]);
                }
                const ulonglong2* hp = (const ulonglong2*)(h0c + k4 * 32);
                ulonglong2 hA0 = hp[0], hB0 = hp[1], hA1 = hp[2], hB1 = hp[3];
                ulonglong2 hA2 = hp[4], hB2 = hp[5], hA3 = hp[6], hB3 = hp[7];
                GRU3(ar, az, an, wr.x, wz.x, wn.x, hA0, hB0);
                GRU3(ar, az, an, wr.y, wz.y, wn.y, hA1, hB1);
                GRU3(ar, az, an, wr.z, wz.z, wn.z, hA2, hB2);
                GRU3(ar, az, an, wr.w, wz.w, wn.w, hA3, hB3);
            }
        }
        {
            float h0new[8];
            #pragma unroll
            for (int p = 0; p < 4; p++) {
                float2 fr = unpack2(ar[p]), fz = unpack2(az[p]), fn = unpack2(an[p]);
                int i0 = 2 * p, i1 = i0 + 1;
                float rg = sigm(gir[i0] + fr.x);
                float zg = sigm(giz[i0] + fz.x);
                float ng = tanhf(gin[i0] + rg * fn.x);
                h0new[i0] = (1.0f - zg) * ng + zg * h0c[t * 8 + i0];
                rg = sigm(gir[i1] + fr.y);
                zg = sigm(giz[i1] + fz.y);
                ng = tanhf(gin[i1] + rg * fn.y);
                h0new[i1] = (1.0f - zg) * ng + zg * h0c[t * 8 + i1];
            }
            *(float4*)(h0n + t * 8)     = make_float4(h0new[0], h0new[1], h0new[2], h0new[3]);
            *(float4*)(h0n + t * 8 + 4) = make_float4(h0new[4], h0new[5], h0new[6], h0new[7]);
        }
        __syncthreads();                                   // S1

        // ===== layer 1 (ALL 256 threads: unit=u1, rows rb1..rb1+3) =========
        {
            ull a1r[2], a1z[2], a1i[2], a1h[2];
            a1r[0] = a1r[1] = splat2(b1r);
            a1z[0] = a1z[1] = splat2(b1z);
            a1i[0] = a1i[1] = splat2(b1i);
            a1h[0] = a1h[1] = splat2(b1h);
            {   // gi side: k over 256 (h0 new)
                const float4* Qr = g_P1i;
                const float4* Qz = g_P1i + 8192;
                const float4* Qn = g_P1i + 16384;
                float4 fwr = __ldg(&Qr[u1]), fwz = __ldg(&Qz[u1]), fwn = __ldg(&Qn[u1]);
                #pragma unroll 4
                for (int k4 = 0; k4 < 64; ++k4) {
                    float4 wr = fwr, wz = fwz, wn = fwn;
                    if (k4 < 63) {
                        int o = (k4 + 1) * 128 + u1;
                        fwr = __ldg(&Qr[o]); fwz = __ldg(&Qz[o]); fwn = __ldg(&Qn[o]);
                    }
                    const float* hb = h0n + k4 * 32 + rb1;
                    ulonglong2 hA0 = *(const ulonglong2*)(hb);
                    ulonglong2 hA1 = *(const ulonglong2*)(hb + 8);
                    ulonglong2 hA2 = *(const ulonglong2*)(hb + 16);
                    ulonglong2 hA3 = *(const ulonglong2*)(hb + 24);
                    GRU3H(a1r, a1z, a1i, wr.x, wz.x, wn.x, hA0);
                    GRU3H(a1r, a1z, a1i, wr.y, wz.y, wn.y, hA1);
                    GRU3H(a1r, a1z, a1i, wr.z, wz.z, wn.z, hA2);
                    GRU3H(a1r, a1z, a1i, wr.w, wz.w, wn.w, hA3);
                }
            }
            {   // gh side: k over 128 (h1 old)
                const float4* Rr = g_P1h;
                const float4* Rz = g_P1h + 4096;
                const float4* Rn = g_P1h + 8192;
                float4 fwr = __ldg(&Rr[u1]), fwz = __ldg(&Rz[u1]), fwn = __ldg(&Rn[u1]);
                #pragma unroll 4
                for (int k4 = 0; k4 < 32; ++k4) {
                    float4 wr = fwr, wz = fwz, wn = fwn;
                    if (k4 < 31) {
                        int o = (k4 + 1) * 128 + u1;
                        fwr = __ldg(&Rr[o]); fwz = __ldg(&Rz[o]); fwn = __ldg(&Rn[o]);
                    }
                    const float* hb = h1c + k4 * 32 + rb1;
                    ulonglong2 hA0 = *(const ulonglong2*)(hb);
                    ulonglong2 hA1 = *(const ulonglong2*)(hb + 8);
                    ulonglong2 hA2 = *(const ulonglong2*)(hb + 16);
                    ulonglong2 hA3 = *(const ulonglong2*)(hb + 24);
                    GRU3H(a1r, a1z, a1h, wr.x, wz.x, wn.x, hA0);
                    GRU3H(a1r, a1z, a1h, wr.y, wz.y, wn.y, hA1);
                    GRU3H(a1r, a1z, a1h, wr.z, wz.z, wn.z, hA2);
                    GRU3H(a1r, a1z, a1h, wr.w, wz.w, wn.w, hA3);
                }
            }
            float h1new[4];
            #pragma unroll
            for (int p = 0; p < 2; p++) {
                float2 fr = unpack2(a1r[p]), fz = unpack2(a1z[p]);
                float2 fi = unpack2(a1i[p]), fh = unpack2(a1h[p]);
                int j0 = 2 * p, j1 = j0 + 1;
                float rg = sigm(fr.x), zg = sigm(fz.x);
                float ng = tanhf(fi.x + rg * fh.x);
                h1new[j0] = (1.0f - zg) * ng + zg * h1c[u1 * 8 + rb1 + j0];
                rg = sigm(fr.y); zg = sigm(fz.y);
                ng = tanhf(fi.y + rg * fh.y);
                h1new[j1] = (1.0f - zg) * ng + zg * h1c[u1 * 8 + rb1 + j1];
            }
            *(float4*)(h1n + u1 * 8 + rb1) = make_float4(h1new[0], h1new[1], h1new[2], h1new[3]);
        }
        __syncthreads();                                   // S2

        // ===== layer 2 (threads 0..127: unit=u2, rows rb2..rb2+1) ==========
        if (t < 128) {
            ull a2r = splat2(b2r), a2z = splat2(b2z);
            ull a2i = splat2(b2i), a2h = splat2(b2h);
            {   // gi side: k over 128 (h1 new)
                const float4* Qr = g_P2i;
                const float4* Qz = g_P2i + 1024;
                const float4* Qn = g_P2i + 2048;
                float4 fwr = __ldg(&Qr[u2]), fwz = __ldg(&Qz[u2]), fwn = __ldg(&Qn[u2]);
                #pragma unroll 4
                for (int k4 = 0; k4 < 32; ++k4) {
                    float4 wr = fwr, wz = fwz, wn = fwn;
                    if (k4 < 31) {
                        int o = (k4 + 1) * 32 + u2;
                        fwr = __ldg(&Qr[o]); fwz = __ldg(&Qz[o]); fwn = __ldg(&Qn[o]);
                    }
                    const float* hb = h1n + k4 * 32 + rb2;
                    ull hv0 = *(const ull*)(hb);
                    ull hv1 = *(const ull*)(hb + 8);
                    ull hv2 = *(const ull*)(hb + 16);
                    ull hv3 = *(const ull*)(hb + 24);
                    GRU3Q(a2r, a2z, a2i, wr.x, wz.x, wn.x, hv0);
                    GRU3Q(a2r, a2z, a2i, wr.y, wz.y, wn.y, hv1);
                    GRU3Q(a2r, a2z, a2i, wr.z, wz.z, wn.z, hv2);
                    GRU3Q(a2r, a2z, a2i, wr.w, wz.w, wn.w, hv3);
                }
            }
            {   // gh side: k over 32 (h2 old)
                const float4* Rr = g_P2h;
                const float4* Rz = g_P2h + 256;
                const float4* Rn = g_P2h + 512;
                float4 fwr = __ldg(&Rr[u2]), fwz = __ldg(&Rz[u2]), fwn = __ldg(&Rn[u2]);
                #pragma unroll
                for (int k4 = 0; k4 < 8; ++k4) {
                    float4 wr = fwr, wz = fwz, wn = fwn;
                    if (k4 < 7) {
                        int o = (k4 + 1) * 32 + u2;
                        fwr = __ldg(&Rr[o]); fwz = __ldg(&Rz[o]); fwn = __ldg(&Rn[o]);
                    }
                    const float* hb = h2c + k4 * 32 + rb2;
                    ull hv0 = *(const ull*)(hb);
                    ull hv1 = *(const ull*)(hb + 8);
                    ull hv2 = *(const ull*)(hb + 16);
                    ull hv3 = *(const ull*)(hb + 24);
                    GRU3Q(a2r, a2z, a2h, wr.x, wz.x, wn.x, hv0);
                    GRU3Q(a2r, a2z, a2h, wr.y, wz.y, wn.y, hv1);
                    GRU3Q(a2r, a2z, a2h, wr.z, wz.z, wn.z, hv2);
                    GRU3Q(a2r, a2z, a2h, wr.w, wz.w, wn.w, hv3);
                }
            }
            float2 fr = unpack2(a2r), fz = unpack2(a2z);
            float2 fi = unpack2(a2i), fh = unpack2(a2h);
            float rg = sigm(fr.x), zg = sigm(fz.x);
            float ng = tanhf(fi.x + rg * fh.x);
            float n0 = (1.0f - zg) * ng + zg * h2c[u2 * 8 + rb2];
            rg = sigm(fr.y); zg = sigm(fz.y);
            ng = tanhf(fi.y + rg * fh.y);
            float n1 = (1.0f - zg) * ng + zg * h2c[u2 * 8 + rb2 + 1];
            *(float2*)(h2n + u2 * 8 + rb2) = make_float2(n0, n1);
        }
        __syncthreads();                                   // S3

        // ================= projection + argmax =============================
        for (int idx = t; idx < VV * ROWS; idx += 256) {
            int r = idx / VV, v = idx - r * VV;
            float acc = bprjS[v];
            #pragma unroll
            for (int k = 0; k < 32; k++)
                acc += h2n[k * 8 + r] * projS[k * VV + v];
            out[((size_t)(row0 + r) * SS + step) * VV + v] = acc;
            slog[v * 8 + r] = acc;
        }
        __syncthreads();                                   // S4
        if (t < ROWS && write_pred) {
            float best = slog[t]; int bi = 0;
            #pragma unroll
            for (int v = 1; v < VV; v++) {
                float x = slog[v * 8 + t];
                if (x > best) { best = x; bi = v; }
            }
            pred[(size_t)(row0 + t) * SS + step] = (float)bi;
        }
        cur = nxt;
    }
}

// ------------------------- launch ------------------------------------------
extern "C" void kernel_launch(void* const* d_in, const int* in_sizes, int n_in,
                              void* d_out, int out_size) {
    const float* latent = (const float*)d_in[0];
    const int*   target = (const int*)  d_in[1];
    const float* W_emb  = (const float*)d_in[2];
    const float* b_emb  = (const float*)d_in[3];
    const float* W_init = (const float*)d_in[4];
    const float* b_init = (const float*)d_in[5];
    const float* Wih0   = (const float*)d_in[6];
    const float* Whh0   = (const float*)d_in[7];
    const float* bih0   = (const float*)d_in[8];
    const float* bhh0   = (const float*)d_in[9];
    const float* Wih1   = (const float*)d_in[10];
    const float* Whh1   = (const float*)d_in[11];
    const float* bih1   = (const float*)d_in[12];
    const float* bhh1   = (const float*)d_in[13];
    const float* Wih2   = (const float*)d_in[14];
    const float* Whh2   = (const float*)d_in[15];
    const float* bih2   = (const float*)d_in[16];
    const float* bhh2   = (const float*)d_in[17];
    const float* W_proj = (const float*)d_in[18];
    const float* b_proj = (const float*)d_in[19];
    (void)in_sizes; (void)n_in;

    k_pre<<<649, 256>>>(latent, b_init, W_init, W_emb, b_emb, bih0,
                        Wih0, Whh0, Wih1, Whh1, Wih2, Whh2, W_proj);

    cudaFuncSetAttribute(k_main, cudaFuncAttributeMaxDynamicSharedMemorySize,
                         SMEM_BYTES);

    float* out  = (float*)d_out;
    float* pred = out + (size_t)BB * SS * VV;
    int wp = (out_size >= (int)((size_t)BB * SS * VV + (size_t)BB * SS)) ? 1 : 0;

    k_main<<<NBLK, 256, SMEM_BYTES>>>(target, bhh0, bih1, bhh1, bih2, bhh2,
                                      b_proj, out, pred, wp);
}

// round 7
// speedup vs baseline: 1.9320x; 1.1892x over previous
#include <cuda_runtime.h>

// ---------------------------------------------------------------------------
// VAE_CDDD_decoder round 6:
//   Round-5 base + (1) static unroll-2 distance-2 double-buffered weight
//   prefetch in L0/L1 GEMM loops (padded arrays, no conditionals),
//   (2) layer-2 weights staged in SMEM, (3) cross-phase weight preloads
//   (L0 chunk0/1 pinned in registers; L1 chunks issued before barriers).
//   Per-output accumulation order unchanged -> bit-identical results.
// ---------------------------------------------------------------------------

#define BB   1024
#define SS   350
#define VV   41
#define ROWS 8
#define NBLK 128

typedef unsigned long long ull;

// ------------------------- device scratch (padded for prefetch overrun) ----
__device__ __align__(16) float4 g_P0 [3 * 64 * 256 + 512];  // Whh0 [g][k4][t]
__device__ __align__(16) float4 g_P1i[3 * 64 * 128 + 256];  // Wih1 [g][k4][u]
__device__ __align__(16) float4 g_P1h[3 * 32 * 128 + 256];  // Whh1
__device__ __align__(16) float4 g_P2i[3 * 32 * 32];         // Wih2
__device__ __align__(16) float4 g_P2h[3 * 8 * 32];          // Whh2
__device__ __align__(16) float  g_G  [VV * 768];            // fused emb->gi
__device__ float g_WprojT[32 * VV];
__device__ float g_hinit [BB * 416];

// ------------------------- helpers -----------------------------------------
__device__ __forceinline__ ull splat2(float w) {
    ull r; asm("mov.b64 %0, {%1, %1};" : "=l"(r) : "f"(w)); return r;
}
__device__ __forceinline__ void fma2(ull& acc, ull a, ull b) {
    asm("fma.rn.f32x2 %0, %1, %2, %0;" : "+l"(acc) : "l"(a), "l"(b));
}
__device__ __forceinline__ float2 unpack2(ull v) {
    float2 f; asm("mov.b64 {%0, %1}, %2;" : "=f"(f.x), "=f"(f.y) : "l"(v)); return f;
}
__device__ __forceinline__ float sigm(float x) { return 1.0f / (1.0f + expf(-x)); }

// 3 gates x 4 accumulators (8 rows) for one k
#define GRU3(aX, aY, aZ, wx, wy, wzc, hA, hB) do { \
    ull w2x = splat2(wx), w2y = splat2(wy), w2z = splat2(wzc); \
    fma2(aX[0], w2x, hA.x); fma2(aX[1], w2x, hA.y); fma2(aX[2], w2x, hB.x); fma2(aX[3], w2x, hB.y); \
    fma2(aY[0], w2y, hA.x); fma2(aY[1], w2y, hA.y); fma2(aY[2], w2y, hB.x); fma2(aY[3], w2y, hB.y); \
    fma2(aZ[0], w2z, hA.x); fma2(aZ[1], w2z, hA.y); fma2(aZ[2], w2z, hB.x); fma2(aZ[3], w2z, hB.y); \
} while (0)

// 3 gates x 2 accumulators (4 rows) for one k
#define GRU3H(aX, aY, aZ, wx, wy, wzc, hA) do { \
    ull w2x = splat2(wx), w2y = splat2(wy), w2z = splat2(wzc); \
    fma2(aX[0], w2x, hA.x); fma2(aX[1], w2x, hA.y); \
    fma2(aY[0], w2y, hA.x); fma2(aY[1], w2y, hA.y); \
    fma2(aZ[0], w2z, hA.x); fma2(aZ[1], w2z, hA.y); \
} while (0)

// 3 gates x 1 accumulator (2 rows) for one k
#define GRU3Q(aX, aY, aZ, wx, wy, wzc, hv) do { \
    ull w2x = splat2(wx), w2y = splat2(wy), w2z = splat2(wzc); \
    fma2(aX, w2x, hv); \
    fma2(aY, w2y, hv); \
    fma2(aZ, w2z, hv); \
} while (0)

// ------------------------- single precompute kernel -------------------------
__global__ void k_pre(
    const float* __restrict__ latent, const float* __restrict__ b_init,
    const float* __restrict__ W_init,
    const float* __restrict__ W_emb,  const float* __restrict__ b_emb,
    const float* __restrict__ bih0,
    const float* __restrict__ Wih0,   const float* __restrict__ Whh0,
    const float* __restrict__ Wih1,   const float* __restrict__ Whh1,
    const float* __restrict__ Wih2,   const float* __restrict__ Whh2,
    const float* __restrict__ W_proj)
{
    __shared__ float sh[4 * 512];
    const int b = blockIdx.x, tid = threadIdx.x;

    if (b < 256) {                       // hinit: 4 batch rows per block
        const int b0 = b * 4;
        for (int i = tid; i < 4 * 512; i += 256)
            sh[i] = latent[b0 * 512 + i];
        __syncthreads();
        for (int j = tid; j < 416; j += 256) {
            const float bi = b_init[j];
            float a0 = bi, a1 = bi, a2 = bi, a3 = bi;
            const float* w = W_init + j * 512;
            for (int k = 0; k < 512; k++) {
                float wv = w[k];
                a0 += wv * sh[k];
                a1 += wv * sh[512 + k];
                a2 += wv * sh[1024 + k];
                a3 += wv * sh[1536 + k];
            }
            g_hinit[(b0 + 0) * 416 + j] = a0;
            g_hinit[(b0 + 1) * 416 + j] = a1;
            g_hinit[(b0 + 2) * 416 + j] = a2;
            g_hinit[(b0 + 3) * 416 + j] = a3;
        }
    } else if (b < 297) {                // G table: one vocab row per block
        const int v = b - 256;
        for (int e = tid; e < 512; e += 256)
            sh[e] = W_emb[e * VV + v] + b_emb[e];
        __syncthreads();
        for (int f = tid; f < 768; f += 256) {
            float acc = bih0[f];
            const float* w = Wih0 + f * 512;
            for (int e = 0; e < 512; e++) acc += sh[e] * w[e];
            g_G[v * 768 + f] = acc;
        }
    } else if (b < 489) {                // pack Whh0 -> P0
        int idx = (b - 297) * 256 + tid;              // < 49152
        int t = idx & 255, k4 = (idx >> 8) & 63, g = idx >> 14;
        g_P0[idx] = *(const float4*)(Whh0 + (g * 256 + t) * 256 + k4 * 4);
    } else if (b < 585) {                // pack Wih1 -> P1i
        int idx = (b - 489) * 256 + tid;              // < 24576
        int u = idx & 127, k4 = (idx >> 7) & 63, g = idx >> 13;
        g_P1i[idx] = *(const float4*)(Wih1 + (g * 128 + u) * 256 + k4 * 4);
    } else if (b < 633) {                // pack Whh1 -> P1h
        int idx = (b - 585) * 256 + tid;              // < 12288
        int u = idx & 127, k4 = (idx >> 7) & 31, g = idx >> 12;
        g_P1h[idx] = *(const float4*)(Whh1 + (g * 128 + u) * 128 + k4 * 4);
    } else if (b < 645) {                // pack Wih2 -> P2i
        int idx = (b - 633) * 256 + tid;              // < 3072
        int u = idx & 31, k4 = (idx >> 5) & 31, g = idx >> 10;
        g_P2i[idx] = *(const float4*)(Wih2 + (g * 32 + u) * 128 + k4 * 4);
    } else if (b < 648) {                // pack Whh2 -> P2h
        int idx = (b - 645) * 256 + tid;              // < 768
        int u = idx & 31, k4 = (idx >> 5) & 7, g = idx >> 8;
        g_P2h[idx] = *(const float4*)(Whh2 + (g * 32 + u) * 32 + k4 * 4);
    } else {                             // proj transpose
        for (int idx = tid; idx < 32 * VV; idx += 256) {
            int k = idx / VV, v = idx - k * VV;
            g_WprojT[idx] = W_proj[v * 32 + k];
        }
    }
}

// ------------------------- main persistent kernel ---------------------------
// smem floats: G 31488 | P2iS 12288 | P2hS 3072 | h0 2*2048 | h1 2*1024 |
//              h2 2*256 | proj 1312 | slog 328 | bproj 41 | + stok 2800 B
#define SM_FLOATS (31488 + 12288 + 3072 + 4096 + 2048 + 512 + 1312 + 328 + 41)
#define SMEM_BYTES (SM_FLOATS * 4 + 2800)

__global__ __launch_bounds__(256, 1) void k_main(
    const int*   __restrict__ target,
    const float* __restrict__ bhh0,
    const float* __restrict__ bih1, const float* __restrict__ bhh1,
    const float* __restrict__ bih2, const float* __restrict__ bhh2,
    const float* __restrict__ bproj,
    float* __restrict__ out, float* __restrict__ pred, int write_pred)
{
    extern __shared__ __align__(16) char smraw[];
    float* Gs    = (float*)smraw;        // 31488
    float* P2iS  = Gs    + 31488;        // 12288
    float* P2hS  = P2iS  + 12288;        // 3072
    float* h0b   = P2hS  + 3072;         // 2 * 2048
    float* h1b   = h0b   + 4096;         // 2 * 1024
    float* h2b   = h1b   + 2048;         // 2 * 256
    float* projS = h2b   + 512;          // 1312
    float* slog  = projS + 1312;         // 328
    float* bprjS = slog  + 328;          // 41
    unsigned char* stok = (unsigned char*)(bprjS + 41);   // 2800

    const int t    = threadIdx.x;
    const int row0 = blockIdx.x * ROWS;

    // ---- stage G + layer-2 weights + proj into SMEM ----
    {
        float4* Gd = (float4*)Gs;
        const float4* Gg = (const float4*)g_G;
        for (int i = t; i < 31488 / 4; i += 256) Gd[i] = Gg[i];
        float4* d2 = (float4*)P2iS;
        for (int i = t; i < 3072; i += 256) d2[i] = g_P2i[i];
        float4* d3 = (float4*)P2hS;
        for (int i = t; i < 768; i += 256) d3[i] = g_P2h[i];
    }
    for (int i = t; i < 1312; i += 256) projS[i] = g_WprojT[i];
    if (t < VV) bprjS[t] = bproj[t];

    // ---- initial hidden state into buffer 0 ----
    #pragma unroll
    for (int r = 0; r < ROWS; r++)
        h0b[t * 8 + r] = g_hinit[(row0 + r) * 416 + t];
    if (t < 128) {
        #pragma unroll
        for (int r = 0; r < ROWS; r++)
            h1b[t * 8 + r] = g_hinit[(row0 + r) * 416 + 256 + t];
    }
    if (t < 32) {
        #pragma unroll
        for (int r = 0; r < ROWS; r++)
            h2b[t * 8 + r] = g_hinit[(row0 + r) * 416 + 384 + t];
    }
    // ---- tokens (teacher forcing: tok[0]=SOS, else target[:,s]) ----
    for (int i = t; i < SS * ROWS; i += 256) {
        int s = i >> 3, r = i & 7;
        int tk = (s == 0) ? 1 : target[(row0 + r) * SS + s];
        stok[i] = (unsigned char)tk;
    }

    // ---- thread mappings + biases in registers ----
    const float b0r = bhh0[t], b0z = bhh0[t + 256], b0n = bhh0[t + 512];

    const int u1  = t & 127;             // layer-1 unit
    const int rb1 = (t >> 7) * 4;        // layer-1 row base (0 or 4)
    const float b1r = bih1[u1] + bhh1[u1];
    const float b1z = bih1[u1 + 128] + bhh1[u1 + 128];
    const float b1i = bih1[u1 + 256];
    const float b1h = bhh1[u1 + 256];

    const int u2  = t & 31;              // layer-2 unit (threads 0..127)
    const int rb2 = ((t >> 5) & 3) * 2;  // layer-2 row base (0,2,4,6)
    float b2r = 0.f, b2z = 0.f, b2i = 0.f, b2h = 0.f;
    if (t < 128) {
        b2r = bih2[u2] + bhh2[u2];
        b2z = bih2[u2 + 32] + bhh2[u2 + 32];
        b2i = bih2[u2 + 64];
        b2h = bhh2[u2 + 64];
    }

    // ---- global weight stream pointers ----
    const float4* Pr = g_P0;
    const float4* Pz = g_P0 + 16384;
    const float4* Pn = g_P0 + 32768;
    const float4* Qr = g_P1i;
    const float4* Qz = g_P1i + 8192;
    const float4* Qn = g_P1i + 16384;
    const float4* Rr = g_P1h;
    const float4* Rz = g_P1h + 4096;
    const float4* Rn = g_P1h + 8192;
    // layer-2 weights now in SMEM
    const float4* Q2r = (const float4*)P2iS;
    const float4* Q2z = Q2r + 1024;
    const float4* Q2n = Q2r + 2048;
    const float4* R2r = (const float4*)P2hS;
    const float4* R2z = R2r + 256;
    const float4* R2n = R2r + 512;

    // ---- PINNED layer-0 weight chunks k4=0,1 (constants across steps) ----
    const float4 PIN0r = __ldg(&Pr[t]),       PIN0z = __ldg(&Pz[t]),       PIN0n = __ldg(&Pn[t]);
    const float4 PIN1r = __ldg(&Pr[256 + t]), PIN1z = __ldg(&Pz[256 + t]), PIN1n = __ldg(&Pn[256 + t]);

    __syncthreads();

    int cur = 0;
    for (int step = 0; step < SS; ++step) {
        const int nxt = cur ^ 1;
        const float* h0c = h0b + cur * 2048;
        float*       h0n = h0b + nxt * 2048;
        const float* h1c = h1b + cur * 1024;
        float*       h1n = h1b + nxt * 1024;
        const float* h2c = h2b + cur * 256;
        float*       h2n = h2b + nxt * 256;

        // ================= layer 0 (256 threads, unit=t, 8 rows) ==========
        float gir[8], giz[8], gin[8];
        #pragma unroll
        for (int r = 0; r < ROWS; r++) {
            int base = (int)stok[step * 8 + r] * 768 + t;
            gir[r] = Gs[base]; giz[r] = Gs[base + 256]; gin[r] = Gs[base + 512];
        }
        ull ar[4], az[4], an[4];
        #pragma unroll
        for (int p = 0; p < 4; p++) { ar[p] = splat2(b0r); az[p] = splat2(b0z); an[p] = splat2(b0n); }
        {
            float4 c0r = PIN0r, c0z = PIN0z, c0n = PIN0n;
            float4 c1r = PIN1r, c1z = PIN1z, c1n = PIN1n;
            for (int k4 = 0; k4 < 64; k4 += 2) {
                const int o2 = (k4 + 2) * 256 + t, o3 = (k4 + 3) * 256 + t;
                float4 c2r = __ldg(&Pr[o2]), c2z = __ldg(&Pz[o2]), c2n = __ldg(&Pn[o2]);
                float4 c3r = __ldg(&Pr[o3]), c3z = __ldg(&Pz[o3]), c3n = __ldg(&Pn[o3]);
                const ulonglong2* hp = (const ulonglong2*)(h0c + k4 * 32);
                ulonglong2 hA0 = hp[0], hB0 = hp[1], hA1 = hp[2], hB1 = hp[3];
                ulonglong2 hA2 = hp[4], hB2 = hp[5], hA3 = hp[6], hB3 = hp[7];
                GRU3(ar, az, an, c0r.x, c0z.x, c0n.x, hA0, hB0);
                GRU3(ar, az, an, c0r.y, c0z.y, c0n.y, hA1, hB1);
                GRU3(ar, az, an, c0r.z, c0z.z, c0n.z, hA2, hB2);
                GRU3(ar, az, an, c0r.w, c0z.w, c0n.w, hA3, hB3);
                hp = (const ulonglong2*)(h0c + k4 * 32 + 32);
                hA0 = hp[0]; hB0 = hp[1]; hA1 = hp[2]; hB1 = hp[3];
                hA2 = hp[4]; hB2 = hp[5]; hA3 = hp[6]; hB3 = hp[7];
                GRU3(ar, az, an, c1r.x, c1z.x, c1n.x, hA0, hB0);
                GRU3(ar, az, an, c1r.y, c1z.y, c1n.y, hA1, hB1);
                GRU3(ar, az, an, c1r.z, c1z.z, c1n.z, hA2, hB2);
                GRU3(ar, az, an, c1r.w, c1z.w, c1n.w, hA3, hB3);
                c0r = c2r; c0z = c2z; c0n = c2n;
                c1r = c3r; c1z = c3z; c1n = c3n;
            }
        }
        // preload layer-1 gi chunks k4=0,1 NOW (in flight across pointwise+S1)
        float4 q0r = __ldg(&Qr[u1]),       q0z = __ldg(&Qz[u1]),       q0n = __ldg(&Qn[u1]);
        float4 q1r = __ldg(&Qr[128 + u1]), q1z = __ldg(&Qz[128 + u1]), q1n = __ldg(&Qn[128 + u1]);
        {
            float h0new[8];
            #pragma unroll
            for (int p = 0; p < 4; p++) {
                float2 fr = unpack2(ar[p]), fz = unpack2(az[p]), fn = unpack2(an[p]);
                int i0 = 2 * p, i1 = i0 + 1;
                float rg = sigm(gir[i0] + fr.x);
                float zg = sigm(giz[i0] + fz.x);
                float ng = tanhf(gin[i0] + rg * fn.x);
                h0new[i0] = (1.0f - zg) * ng + zg * h0c[t * 8 + i0];
                rg = sigm(gir[i1] + fr.y);
                zg = sigm(giz[i1] + fz.y);
                ng = tanhf(gin[i1] + rg * fn.y);
                h0new[i1] = (1.0f - zg) * ng + zg * h0c[t * 8 + i1];
            }
            *(float4*)(h0n + t * 8)     = make_float4(h0new[0], h0new[1], h0new[2], h0new[3]);
            *(float4*)(h0n + t * 8 + 4) = make_float4(h0new[4], h0new[5], h0new[6], h0new[7]);
        }
        __syncthreads();                                   // S1

        // ===== layer 1 (ALL 256 threads: unit=u1, rows rb1..rb1+3) =========
        {
            // preload gh chunks k4=0,1 (consumed after the whole gi loop)
            float4 g0r = __ldg(&Rr[u1]),       g0z = __ldg(&Rz[u1]),       g0n = __ldg(&Rn[u1]);
            float4 g1r = __ldg(&Rr[128 + u1]), g1z = __ldg(&Rz[128 + u1]), g1n = __ldg(&Rn[128 + u1]);

            ull a1r[2], a1z[2], a1i[2], a1h[2];
            a1r[0] = a1r[1] = splat2(b1r);
            a1z[0] = a1z[1] = splat2(b1z);
            a1i[0] = a1i[1] = splat2(b1i);
            a1h[0] = a1h[1] = splat2(b1h);

            // gi side: k over 256 (h0 new), unroll-2 dist-2
            for (int k4 = 0; k4 < 64; k4 += 2) {
                const int o2 = (k4 + 2) * 128 + u1, o3 = (k4 + 3) * 128 + u1;
                float4 c2r = __ldg(&Qr[o2]), c2z = __ldg(&Qz[o2]), c2n = __ldg(&Qn[o2]);
                float4 c3r = __ldg(&Qr[o3]), c3z = __ldg(&Qz[o3]), c3n = __ldg(&Qn[o3]);
                const float* hb = h0n + k4 * 32 + rb1;
                ulonglong2 hA0 = *(const ulonglong2*)(hb);
                ulonglong2 hA1 = *(const ulonglong2*)(hb + 8);
                ulonglong2 hA2 = *(const ulonglong2*)(hb + 16);
                ulonglong2 hA3 = *(const ulonglong2*)(hb + 24);
                GRU3H(a1r, a1z, a1i, q0r.x, q0z.x, q0n.x, hA0);
                GRU3H(a1r, a1z, a1i, q0r.y, q0z.y, q0n.y, hA1);
                GRU3H(a1r, a1z, a1i, q0r.z, q0z.z, q0n.z, hA2);
                GRU3H(a1r, a1z, a1i, q0r.w, q0z.w, q0n.w, hA3);
                hb += 32;
                hA0 = *(const ulonglong2*)(hb);
                hA1 = *(const ulonglong2*)(hb + 8);
                hA2 = *(const ulonglong2*)(hb + 16);
                hA3 = *(const ulonglong2*)(hb + 24);
                GRU3H(a1r, a1z, a1i, q1r.x, q1z.x, q1n.x, hA0);
                GRU3H(a1r, a1z, a1i, q1r.y, q1z.y, q1n.y, hA1);
                GRU3H(a1r, a1z, a1i, q1r.z, q1z.z, q1n.z, hA2);
                GRU3H(a1r, a1z, a1i, q1r.w, q1z.w, q1n.w, hA3);
                q0r = c2r; q0z = c2z; q0n = c2n;
                q1r = c3r; q1z = c3z; q1n = c3n;
            }
            // gh side: k over 128 (h1 old), unroll-2 dist-2
            for (int k4 = 0; k4 < 32; k4 += 2) {
                const int o2 = (k4 + 2) * 128 + u1, o3 = (k4 + 3) * 128 + u1;
                float4 c2r = __ldg(&Rr[o2]), c2z = __ldg(&Rz[o2]), c2n = __ldg(&Rn[o2]);
                float4 c3r = __ldg(&Rr[o3]), c3z = __ldg(&Rz[o3]), c3n = __ldg(&Rn[o3]);
                const float* hb = h1c + k4 * 32 + rb1;
                ulonglong2 hA0 = *(const ulonglong2*)(hb);
                ulonglong2 hA1 = *(const ulonglong2*)(hb + 8);
                ulonglong2 hA2 = *(const ulonglong2*)(hb + 16);
                ulonglong2 hA3 = *(const ulonglong2*)(hb + 24);
                GRU3H(a1r, a1z, a1h, g0r.x, g0z.x, g0n.x, hA0);
                GRU3H(a1r, a1z, a1h, g0r.y, g0z.y, g0n.y, hA1);
                GRU3H(a1r, a1z, a1h, g0r.z, g0z.z, g0n.z, hA2);
                GRU3H(a1r, a1z, a1h, g0r.w, g0z.w, g0n.w, hA3);
                hb += 32;
                hA0 = *(const ulonglong2*)(hb);
                hA1 = *(const ulonglong2*)(hb + 8);
                hA2 = *(const ulonglong2*)(hb + 16);
                hA3 = *(const ulonglong2*)(hb + 24);
                GRU3H(a1r, a1z, a1h, g1r.x, g1z.x, g1n.x, hA0);
                GRU3H(a1r, a1z, a1h, g1r.y, g1z.y, g1n.y, hA1);
                GRU3H(a1r, a1z, a1h, g1r.z, g1z.z, g1n.z, hA2);
                GRU3H(a1r, a1z, a1h, g1r.w, g1z.w, g1n.w, hA3);
                g0r = c2r; g0z = c2z; g0n = c2n;
                g1r = c3r; g1z = c3z; g1n = c3n;
            }
            float h1new[4];
            #pragma unroll
            for (int p = 0; p < 2; p++) {
                float2 fr = unpack2(a1r[p]), fz = unpack2(a1z[p]);
                float2 fi = unpack2(a1i[p]), fh = unpack2(a1h[p]);
                int j0 = 2 * p, j1 = j0 + 1;
                float rg = sigm(fr.x), zg = sigm(fz.x);
                float ng = tanhf(fi.x + rg * fh.x);
                h1new[j0] = (1.0f - zg) * ng + zg * h1c[u1 * 8 + rb1 + j0];
                rg = sigm(fr.y); zg = sigm(fz.y);
                ng = tanhf(fi.y + rg * fh.y);
                h1new[j1] = (1.0f - zg) * ng + zg * h1c[u1 * 8 + rb1 + j1];
            }
            *(float4*)(h1n + u1 * 8 + rb1) = make_float4(h1new[0], h1new[1], h1new[2], h1new[3]);
        }
        __syncthreads();                                   // S2

        // ===== layer 2 (threads 0..127: unit=u2, rows rb2..rb2+1) ==========
        // weights come from SMEM (zero L2 traffic, LDS latency only)
        if (t < 128) {
            ull a2r = splat2(b2r), a2z = splat2(b2z);
            ull a2i = splat2(b2i), a2h = splat2(b2h);
            #pragma unroll 4
            for (int k4 = 0; k4 < 32; ++k4) {            // gi side: h1 new
                float4 wr = Q2r[k4 * 32 + u2];
                float4 wz = Q2z[k4 * 32 + u2];
                float4 wn = Q2n[k4 * 32 + u2];
                const float* hb = h1n + k4 * 32 + rb2;
                ull hv0 = *(const ull*)(hb);
                ull hv1 = *(const ull*)(hb + 8);
                ull hv2 = *(const ull*)(hb + 16);
                ull hv3 = *(const ull*)(hb + 24);
                GRU3Q(a2r, a2z, a2i, wr.x, wz.x, wn.x, hv0);
                GRU3Q(a2r, a2z, a2i, wr.y, wz.y, wn.y, hv1);
                GRU3Q(a2r, a2z, a2i, wr.z, wz.z, wn.z, hv2);
                GRU3Q(a2r, a2z, a2i, wr.w, wz.w, wn.w, hv3);
            }
            #pragma unroll
            for (int k4 = 0; k4 < 8; ++k4) {             // gh side: h2 old
                float4 wr = R2r[k4 * 32 + u2];
                float4 wz = R2z[k4 * 32 + u2];
                float4 wn = R2n[k4 * 32 + u2];
                const float* hb = h2c + k4 * 32 + rb2;
                ull hv0 = *(const ull*)(hb);
                ull hv1 = *(const ull*)(hb + 8);
                ull hv2 = *(const ull*)(hb + 16);
                ull hv3 = *(const ull*)(hb + 24);
                GRU3Q(a2r, a2z, a2h, wr.x, wz.x, wn.x, hv0);
                GRU3Q(a2r, a2z, a2h, wr.y, wz.y, wn.y, hv1);
                GRU3Q(a2r, a2z, a2h, wr.z, wz.z, wn.z, hv2);
                GRU3Q(a2r, a2z, a2h, wr.w, wz.w, wn.w, hv3);
            }
            float2 fr = unpack2(a2r), fz = unpack2(a2z);
            float2 fi = unpack2(a2i), fh = unpack2(a2h);
            float rg = sigm(fr.x), zg = sigm(fz.x);
            float ng = tanhf(fi.x + rg * fh.x);
            float n0 = (1.0f - zg) * ng + zg * h2c[u2 * 8 + rb2];
            rg = sigm(fr.y); zg = sigm(fz.y);
            ng = tanhf(fi.y + rg * fh.y);
            float n1 = (1.0f - zg) * ng + zg * h2c[u2 * 8 + rb2 + 1];
            *(float2*)(h2n + u2 * 8 + rb2) = make_float2(n0, n1);
        }
        __syncthreads();                                   // S3

        // ================= projection + argmax =============================
        for (int idx = t; idx < VV * ROWS; idx += 256) {
            int r = idx / VV, v = idx - r * VV;
            float acc = bprjS[v];
            #pragma unroll
            for (int k = 0; k < 32; k++)
                acc += h2n[k * 8 + r] * projS[k * VV + v];
            out[((size_t)(row0 + r) * SS + step) * VV + v] = acc;
            slog[v * 8 + r] = acc;
        }
        __syncthreads();                                   // S4
        if (t < ROWS && write_pred) {
            float best = slog[t]; int bi = 0;
            #pragma unroll
            for (int v = 1; v < VV; v++) {
                float x = slog[v * 8 + t];
                if (x > best) { best = x; bi = v; }
            }
            pred[(size_t)(row0 + t) * SS + step] = (float)bi;
        }
        cur = nxt;
    }
}

// ------------------------- launch ------------------------------------------
extern "C" void kernel_launch(void* const* d_in, const int* in_sizes, int n_in,
                              void* d_out, int out_size) {
    const float* latent = (const float*)d_in[0];
    const int*   target = (const int*)  d_in[1];
    const float* W_emb  = (const float*)d_in[2];
    const float* b_emb  = (const float*)d_in[3];
    const float* W_init = (const float*)d_in[4];
    const float* b_init = (const float*)d_in[5];
    const float* Wih0   = (const float*)d_in[6];
    const float* Whh0   = (const float*)d_in[7];
    const float* bih0   = (const float*)d_in[8];
    const float* bhh0   = (const float*)d_in[9];
    const float* Wih1   = (const float*)d_in[10];
    const float* Whh1   = (const float*)d_in[11];
    const float* bih1   = (const float*)d_in[12];
    const float* bhh1   = (const float*)d_in[13];
    const float* Wih2   = (const float*)d_in[14];
    const float* Whh2   = (const float*)d_in[15];
    const float* bih2   = (const float*)d_in[16];
    const float* bhh2   = (const float*)d_in[17];
    const float* W_proj = (const float*)d_in[18];
    const float* b_proj = (const float*)d_in[19];
    (void)in_sizes; (void)n_in;

    k_pre<<<649, 256>>>(latent, b_init, W_init, W_emb, b_emb, bih0,
                        Wih0, Whh0, Wih1, Whh1, Wih2, Whh2, W_proj);

    cudaFuncSetAttribute(k_main, cudaFuncAttributeMaxDynamicSharedMemorySize,
                         SMEM_BYTES);

    float* out  = (float*)d_out;
    float* pred = out + (size_t)BB * SS * VV;
    int wp = (out_size >= (int)((size_t)BB * SS * VV + (size_t)BB * SS)) ? 1 : 0;

    k_main<<<NBLK, 256, SMEM_BYTES>>>(target, bhh0, bih1, bhh1, bih2, bhh2,
                                      b_proj, out, pred, wp);
}